// round 15
// baseline (speedup 1.0000x reference)
#include <cuda_runtime.h>
#include <cstdint>

// Problem constants
#define B 32
#define N 4096
#define KDIM 4096
#define KK 16                // k floats per pipeline stage (half-chunk)
#define NCHUNK (KDIM / KK)   // 256
#define TO 256               // output tile per block
#define KS_QKV 6
#define KS_P 18
#define SLABS 18
#define NBINS 128
#define LOG2E 1.4426950408889634f
#define BIASC2 1.000704f     // tf32 RZ-truncation bias correction, both operands

#define ROWPAD 20            // floats per smem row (16 data + 4 pad)
#define X_OFF (TO * ROWPAD)          // 5120 floats
#define SBUF ((TO + B) * ROWPAD)     // 5760 floats per stage
#define NSTAGE 4
#define GEMM_SMEM (NSTAGE * SBUF * 4)   // 92160 bytes

// Scratch (static device allocations — allowed)
__device__ float g_part[SLABS][B][N];   // partial GEMM sums
__device__ float g_h[B][N];             // h = silu(x + attended)
// Per-batch bin moments for rank-1 attention
__device__ float4 g_mD[B][NBINS];
__device__ float4 g_mA[B][NBINS];
__device__ float2 g_mE[B][NBINS];
__device__ float2 g_binfo[B];

__device__ __forceinline__ uint32_t sm_u32(const void* p) {
    return (uint32_t)__cvta_generic_to_shared(p);
}
#define CP_ASYNC16(dst, src) \
    asm volatile("cp.async.cg.shared.global [%0], [%1], 16;" :: "r"(dst), "l"(src))
#define CP_COMMIT() asm volatile("cp.async.commit_group;")

__device__ __forceinline__ float fast_exp2(float x) {
    float y;
    asm("ex2.approx.ftz.f32 %0, %1;" : "=f"(y) : "f"(x));
    return y;
}

// ---- packed f32x2 helpers ----
__device__ __forceinline__ uint64_t packf2(float lo, float hi) {
    uint64_t r;
    asm("mov.b64 %0, {%1, %2};" : "=l"(r) : "f"(lo), "f"(hi));
    return r;
}
__device__ __forceinline__ void unpackf2(uint64_t v, float& lo, float& hi) {
    asm("mov.b64 {%0, %1}, %2;" : "=f"(lo), "=f"(hi) : "l"(v));
}
__device__ __forceinline__ uint64_t fma2(uint64_t a, uint64_t b, uint64_t c) {
    uint64_t d;
    asm("fma.rn.f32x2 %0, %1, %2, %3;" : "=l"(d) : "l"(a), "l"(b), "l"(c));
    return d;
}

__device__ __forceinline__ void mma_tf32(
    float* d, uint32_t a0, uint32_t a1, uint32_t a2, uint32_t a3,
    uint32_t b0, uint32_t b1)
{
    asm volatile(
        "mma.sync.aligned.m16n8k8.row.col.f32.tf32.tf32.f32 "
        "{%0,%1,%2,%3}, {%4,%5,%6,%7}, {%8,%9}, {%0,%1,%2,%3};"
        : "+f"(d[0]), "+f"(d[1]), "+f"(d[2]), "+f"(d[3])
        : "r"(a0), "r"(a1), "r"(a2), "r"(a3), "r"(b0), "r"(b1));
}

// ---------------------------------------------------------------------------
// GEMM via mma.sync tf32: g_part[slab][b][o] = sum_k W[o,k]*X[b,k]
// Both operands raw fp32 (HW RZ-truncation to tf32), BIASC2 epilogue fix.
// 4-stage cp.async ring on 16-float half-chunks: prefetch depth 3 keeps DRAM
// streaming continuously (R13 profile showed depth-1 left DRAM at 48%).
// Rows padded to 20 floats: fragment LDS banks {g*20+t} all distinct.
// ---------------------------------------------------------------------------
__global__ __launch_bounds__(256, 2) void gemm_kernel(
    const float* __restrict__ X,
    const float* __restrict__ W0, const float* __restrict__ W1,
    const float* __restrict__ W2,
    int KS)
{
    extern __shared__ float sm[];

    const float* W = (blockIdx.y == 0) ? W0 : ((blockIdx.y == 1) ? W1 : W2);
    const int obase = blockIdx.x * TO;
    const int s = blockIdx.z;
    const int c0 = (NCHUNK * s) / KS;
    const int c1 = (NCHUNK * (s + 1)) / KS;
    const int NC = c1 - c0;

    const int tid = threadIdx.x;
    const int wid = tid >> 5;
    const int lane = tid & 31;
    const int g = lane >> 2;
    const int t = lane & 3;
    const int m0 = wid * 32;

    // loader slots: 4 threads per row, 4 float4 cols (16 floats)
    const int lrow = tid >> 2;
    const int lc4 = (tid & 3) * 4;

    auto issue = [&](int c, float* buf) {
        #pragma unroll
        for (int i = 0; i < 4; i++) {
            int row = lrow + 64 * i;
            uint32_t dst = sm_u32(&buf[row * ROWPAD + lc4]);
            const float* src = W + (size_t)(obase + row) * KDIM + c * KK + lc4;
            CP_ASYNC16(dst, src);
        }
        if (tid < 4 * B) {
            uint32_t dx = sm_u32(&buf[X_OFF + lrow * ROWPAD + lc4]);
            const float* sx = X + (size_t)lrow * KDIM + c * KK + lc4;
            CP_ASYNC16(dx, sx);
        }
        CP_COMMIT();
    };

    int issued = 0;
    #pragma unroll
    for (int i = 0; i < NSTAGE; i++)
        if (issued < NC) { issue(c0 + issued, sm + (issued & 3) * SBUF); issued++; }

    float d[2][4][4];
    #pragma unroll
    for (int mi = 0; mi < 2; mi++)
        #pragma unroll
        for (int nt = 0; nt < 4; nt++)
            #pragma unroll
            for (int r = 0; r < 4; r++) d[mi][nt][r] = 0.0f;

    for (int idx = 0; idx < NC; idx++) {
        const int pend = issued - idx - 1;
        if (pend >= 3)      asm volatile("cp.async.wait_group 3;");
        else if (pend == 2) asm volatile("cp.async.wait_group 2;");
        else if (pend == 1) asm volatile("cp.async.wait_group 1;");
        else                asm volatile("cp.async.wait_group 0;");
        __syncthreads();

        const float* Ws = sm + (idx & 3) * SBUF;
        const float* Xs = Ws + X_OFF;

        #pragma unroll
        for (int ks = 0; ks < 2; ks++) {
            const int k0 = ks * 8;
            uint32_t a[2][4];
            #pragma unroll
            for (int mi = 0; mi < 2; mi++) {
                const float* wr = Ws + (m0 + 16 * mi) * ROWPAD + k0;
                a[mi][0] = __float_as_uint(wr[g * ROWPAD + t]);
                a[mi][1] = __float_as_uint(wr[(g + 8) * ROWPAD + t]);
                a[mi][2] = __float_as_uint(wr[g * ROWPAD + t + 4]);
                a[mi][3] = __float_as_uint(wr[(g + 8) * ROWPAD + t + 4]);
            }
            #pragma unroll
            for (int nt = 0; nt < 4; nt++) {
                const int brow = (nt * 8 + g) * ROWPAD + k0;
                uint32_t b0 = __float_as_uint(Xs[brow + t]);
                uint32_t b1 = __float_as_uint(Xs[brow + t + 4]);
                mma_tf32(d[0][nt], a[0][0], a[0][1], a[0][2], a[0][3], b0, b1);
                mma_tf32(d[1][nt], a[1][0], a[1][1], a[1][2], a[1][3], b0, b1);
            }
        }
        __syncthreads();
        if (issued < NC) { issue(c0 + issued, sm + (issued & 3) * SBUF); issued++; }
    }

    // Epilogue: D fragment (m16 x n8): d0:(g,2t) d1:(g,2t+1) d2:(g+8,2t)
    // d3:(g+8,2t+1); rows = o, cols = batch.
    const int slab = blockIdx.y * KS + s;
    #pragma unroll
    for (int mi = 0; mi < 2; mi++) {
        const int o = obase + m0 + 16 * mi + g;
        #pragma unroll
        for (int nt = 0; nt < 4; nt++) {
            const int bb = nt * 8 + 2 * t;
            g_part[slab][bb][o]         = d[mi][nt][0] * BIASC2;
            g_part[slab][bb + 1][o]     = d[mi][nt][1] * BIASC2;
            g_part[slab][bb][o + 8]     = d[mi][nt][2] * BIASC2;
            g_part[slab][bb + 1][o + 8] = d[mi][nt][3] * BIASC2;
        }
    }
}

// ---------------------------------------------------------------------------
// Moments kernel (slabs: k=6..11, v=12..17)
// ---------------------------------------------------------------------------
__global__ __launch_bounds__(256) void moments_kernel(
    const float* __restrict__ bk, const float* __restrict__ bv)
{
    extern __shared__ float dsm[];
    float* ksm = dsm;                 // [N]
    float* vsm = dsm + N;             // [N]
    float* rep = dsm + 2 * N;         // [8][NBINS][10]
    __shared__ float red[16];

    const int b = blockIdx.x;
    const int tid = threadIdx.x;
    const int w = tid >> 5;
    const int lane = tid & 31;

    float kmn = 1e30f, kmx = -1e30f;
    for (int j = tid; j < N; j += 256) {
        float kv = bk[j], vv = bv[j];
        #pragma unroll
        for (int s = 0; s < KS_QKV; s++) {
            kv += g_part[KS_QKV + s][b][j];
            vv += g_part[2 * KS_QKV + s][b][j];
        }
        ksm[j] = kv;
        vsm[j] = vv;
        kmn = fminf(kmn, kv);
        kmx = fmaxf(kmx, kv);
    }
    #pragma unroll
    for (int d = 16; d > 0; d >>= 1) {
        kmn = fminf(kmn, __shfl_xor_sync(0xffffffffu, kmn, d));
        kmx = fmaxf(kmx, __shfl_xor_sync(0xffffffffu, kmx, d));
    }
    if (lane == 0) { red[w] = kmn; red[8 + w] = kmx; }

    for (int tt = tid; tt < 8 * NBINS * 10; tt += 256) rep[tt] = 0.0f;
    __syncthreads();

    float bmn = red[0], bmx = red[8];
    #pragma unroll
    for (int ww = 1; ww < 8; ww++) {
        bmn = fminf(bmn, red[ww]);
        bmx = fmaxf(bmx, red[8 + ww]);
    }
    float range = fmaxf(bmx - bmn, 1e-6f);
    float dlt = exp2f(ceilf(log2f(range / 126.0f)));
    float kmin_a = floorf(bmn / dlt) * dlt;
    float inv_d = 1.0f / dlt;

    float* myrep = rep + w * (NBINS * 10);
    for (int j = tid; j < N; j += 256) {
        float k = ksm[j], v = vsm[j];
        float cf = (k - kmin_a) * inv_d;
        int c = (int)cf;
        c = max(0, min(NBINS - 1, c));
        float eps = k - fmaf((float)c + 0.5f, dlt, kmin_a);
        float p1 = eps;
        float p2 = 0.5f * eps * eps;
        float p3 = p2 * eps * (1.0f / 3.0f);
        float p4 = p3 * eps * 0.25f;
        float* r = myrep + c * 10;
        atomicAdd(r + 0, 1.0f);
        atomicAdd(r + 1, p1);
        atomicAdd(r + 2, p2);
        atomicAdd(r + 3, p3);
        atomicAdd(r + 4, p4);
        atomicAdd(r + 5, v);
        atomicAdd(r + 6, v * p1);
        atomicAdd(r + 7, v * p2);
        atomicAdd(r + 8, v * p3);
        atomicAdd(r + 9, v * p4);
    }
    __syncthreads();

    if (tid < NBINS) {
        int c = tid;
        float m[10];
        #pragma unroll
        for (int mm = 0; mm < 10; mm++) {
            float sum = 0.0f;
            #pragma unroll
            for (int ww = 0; ww < 8; ww++)
                sum += rep[ww * (NBINS * 10) + c * 10 + mm];
            m[mm] = sum;
        }
        g_mD[b][c] = make_float4(m[0], m[1], m[2], m[3]);
        g_mA[b][c] = make_float4(m[5], m[6], m[7], m[8]);
        g_mE[b][c] = make_float2(m[4], m[9]);
        if (c == 0)
            g_binfo[b] = make_float2(kmin_a + 0.5f * dlt, dlt);
    }
}

// ---------------------------------------------------------------------------
// Attention via bin moments + first SiLU. Geometric exp recurrence: bins are
// equidistant so e_{c+2} = e_c * r2 with r2 = exp2(qL*2*dlt) — replaces
// per-bin MUFU with one FMUL. 2-bin unroll, independent (e, dn) chains.
// ---------------------------------------------------------------------------
__global__ __launch_bounds__(256) void attn2_kernel(
    const float* __restrict__ X, const float* __restrict__ bq)
{
    __shared__ uint64_t sDA[NBINS * 5];   // [c][m]: pair (D_m, A_m)
    const int b = blockIdx.y;
    const int tid = threadIdx.x;

    if (tid < NBINS) {
        float4 D = g_mD[b][tid];
        float4 A = g_mA[b][tid];
        float2 E = g_mE[b][tid];
        sDA[tid * 5 + 0] = packf2(D.x, A.x);
        sDA[tid * 5 + 1] = packf2(D.y, A.y);
        sDA[tid * 5 + 2] = packf2(D.z, A.z);
        sDA[tid * 5 + 3] = packf2(D.w, A.w);
        sDA[tid * 5 + 4] = packf2(E.x, E.y);
    }
    __syncthreads();

    const int i = blockIdx.x * 256 + tid;
    float q = bq[i];
    #pragma unroll
    for (int s = 0; s < KS_QKV; s++) q += g_part[s][b][i];

    const float2 info = g_binfo[b];
    const float kc0 = info.x;
    const float dlt = info.y;
    const float qL = q * LOG2E;
    const uint64_t qq = packf2(q, q);

    float e0 = fast_exp2(qL * kc0);
    float e1 = fast_exp2(qL * (kc0 + dlt));
    const float r2 = fast_exp2(qL * (2.0f * dlt));

    uint64_t dn0 = 0ull, dn1 = 0ull;
    #pragma unroll 4
    for (int c = 0; c < NBINS / 2; c++) {
        const uint64_t* m0 = &sDA[(2 * c) * 5];
        const uint64_t* m1 = &sDA[(2 * c + 1) * 5];
        uint64_t p0 = fma2(m0[4], qq, m0[3]);
        uint64_t p1 = fma2(m1[4], qq, m1[3]);
        p0 = fma2(p0, qq, m0[2]);
        p1 = fma2(p1, qq, m1[2]);
        p0 = fma2(p0, qq, m0[1]);
        p1 = fma2(p1, qq, m1[1]);
        p0 = fma2(p0, qq, m0[0]);
        p1 = fma2(p1, qq, m1[0]);
        dn0 = fma2(packf2(e0, e0), p0, dn0);
        dn1 = fma2(packf2(e1, e1), p1, dn1);
        e0 *= r2;
        e1 *= r2;
    }
    float den0, num0, den1, num1;
    unpackf2(dn0, den0, num0);
    unpackf2(dn1, den1, num1);
    float den = den0 + den1;
    float num = num0 + num1;

    float att = num / den;
    float z = X[(size_t)b * N + i] + att;
    float sg = 1.0f / (1.0f + fast_exp2(-z * LOG2E));
    g_h[b][i] = z * sg;
}

// ---------------------------------------------------------------------------
// Final reduce: out = silu(h + (h @ Wp^T + bp))
// ---------------------------------------------------------------------------
__global__ __launch_bounds__(256) void final_kernel(
    const float* __restrict__ bp, float* __restrict__ out)
{
    const int idx = blockIdx.x * 256 + threadIdx.x;
    const int b = idx >> 12;
    const int o = idx & (N - 1);
    float p = bp[o];
    #pragma unroll
    for (int s = 0; s < SLABS; s++) p += g_part[s][b][o];
    float z = g_h[b][o] + p;
    float sg = 1.0f / (1.0f + fast_exp2(-z * LOG2E));
    out[idx] = z * sg;
}

// ---------------------------------------------------------------------------
extern "C" void kernel_launch(void* const* d_in, const int* in_sizes, int n_in,
                              void* d_out, int out_size)
{
    const float* x  = (const float*)d_in[0];
    const float* Wq = (const float*)d_in[1];
    const float* bq = (const float*)d_in[2];
    const float* Wk = (const float*)d_in[3];
    const float* bk = (const float*)d_in[4];
    const float* Wv = (const float*)d_in[5];
    const float* bv = (const float*)d_in[6];
    const float* Wp = (const float*)d_in[7];
    const float* bp = (const float*)d_in[8];
    float* out = (float*)d_out;

    cudaFuncSetAttribute(gemm_kernel,
                         cudaFuncAttributeMaxDynamicSharedMemorySize, GEMM_SMEM);
    const int mom_smem = (2 * N + 8 * NBINS * 10) * (int)sizeof(float);
    cudaFuncSetAttribute(moments_kernel,
                         cudaFuncAttributeMaxDynamicSharedMemorySize, mom_smem);

    void* hptr = nullptr;
    cudaGetSymbolAddress(&hptr, g_h);

    // q,k,v GEMMs: slabs q=0..5, k=6..11, v=12..17
    gemm_kernel<<<dim3(N / TO, 3, KS_QKV), 256, GEMM_SMEM>>>(
        x, Wq, Wk, Wv, KS_QKV);
    // per-batch bin moments
    moments_kernel<<<B, 256, mom_smem>>>(bk, bv);
    // attention + silu -> g_h (q: slabs 0..5)
    attn2_kernel<<<dim3(N / 256, B), 256>>>(x, bq);
    // projection GEMM on h: slabs 0..17
    gemm_kernel<<<dim3(N / TO, 1, KS_P), 256, GEMM_SMEM>>>(
        (const float*)hptr, Wp, Wp, Wp, KS_P);
    // final reduce + silu
    final_kernel<<<(B * N) / 256, 256>>>(bp, out);
}

// round 17
// speedup vs baseline: 1.0028x; 1.0028x over previous
#include <cuda_runtime.h>
#include <cstdint>

// Problem constants
#define B 32
#define N 4096
#define KDIM 4096
#define KK 32                // k floats per pipeline stage (128-B rows)
#define NCHUNK (KDIM / KK)   // 128
#define TO 128               // output tile per block (halved for depth-4 ring)
#define KS_QKV 6
#define KS_P 18
#define SLABS 18
#define NBINS 128
#define LOG2E 1.4426950408889634f
#define BIASC2 1.000704f     // tf32 RZ-truncation bias correction, both operands

#define ROWPAD 36            // floats per smem row (32 data + 4 pad)
#define X_OFF (TO * ROWPAD)          // 4608 floats
#define SBUF ((TO + B) * ROWPAD)     // 5760 floats per stage
#define NSTAGE 4
#define GEMM_SMEM (NSTAGE * SBUF * 4)   // 92160 bytes

// Scratch (static device allocations — allowed)
__device__ float g_part[SLABS][B][N];   // partial GEMM sums
__device__ float g_h[B][N];             // h = silu(x + attended)
// Per-batch bin moments for rank-1 attention
__device__ float4 g_mD[B][NBINS];
__device__ float4 g_mA[B][NBINS];
__device__ float2 g_mE[B][NBINS];
__device__ float2 g_binfo[B];

__device__ __forceinline__ uint32_t sm_u32(const void* p) {
    return (uint32_t)__cvta_generic_to_shared(p);
}
#define CP_ASYNC16(dst, src) \
    asm volatile("cp.async.cg.shared.global [%0], [%1], 16;" :: "r"(dst), "l"(src))
#define CP_COMMIT() asm volatile("cp.async.commit_group;")

__device__ __forceinline__ float fast_exp2(float x) {
    float y;
    asm("ex2.approx.ftz.f32 %0, %1;" : "=f"(y) : "f"(x));
    return y;
}

// ---- packed f32x2 helpers ----
__device__ __forceinline__ uint64_t packf2(float lo, float hi) {
    uint64_t r;
    asm("mov.b64 %0, {%1, %2};" : "=l"(r) : "f"(lo), "f"(hi));
    return r;
}
__device__ __forceinline__ void unpackf2(uint64_t v, float& lo, float& hi) {
    asm("mov.b64 {%0, %1}, %2;" : "=f"(lo), "=f"(hi) : "l"(v));
}
__device__ __forceinline__ uint64_t fma2(uint64_t a, uint64_t b, uint64_t c) {
    uint64_t d;
    asm("fma.rn.f32x2 %0, %1, %2, %3;" : "=l"(d) : "l"(a), "l"(b), "l"(c));
    return d;
}

__device__ __forceinline__ void mma_tf32(
    float* d, uint32_t a0, uint32_t a1, uint32_t a2, uint32_t a3,
    uint32_t b0, uint32_t b1)
{
    asm volatile(
        "mma.sync.aligned.m16n8k8.row.col.f32.tf32.tf32.f32 "
        "{%0,%1,%2,%3}, {%4,%5,%6,%7}, {%8,%9}, {%0,%1,%2,%3};"
        : "+f"(d[0]), "+f"(d[1]), "+f"(d[2]), "+f"(d[3])
        : "r"(a0), "r"(a1), "r"(a2), "r"(a3), "r"(b0), "r"(b1));
}

// ---------------------------------------------------------------------------
// GEMM via mma.sync tf32: g_part[slab][b][o] = sum_k W[o,k]*X[b,k]
// Both operands raw fp32 (HW RZ-truncation to tf32), BIASC2 epilogue fix.
// TO=128 o-rows x 32 batches per CTA; KK=32 chunks (128-B rows) in a 4-stage
// cp.async ring -> 3 chunks always in flight, DRAM streams continuously.
// Rows padded to 36 floats: fragment LDS conflict-free (proven layout).
// ---------------------------------------------------------------------------
__global__ __launch_bounds__(256, 2) void gemm_kernel(
    const float* __restrict__ X,
    const float* __restrict__ W0, const float* __restrict__ W1,
    const float* __restrict__ W2,
    int KS)
{
    extern __shared__ float sm[];

    const float* W = (blockIdx.y == 0) ? W0 : ((blockIdx.y == 1) ? W1 : W2);
    const int obase = blockIdx.x * TO;
    const int s = blockIdx.z;
    const int c0 = (NCHUNK * s) / KS;
    const int c1 = (NCHUNK * (s + 1)) / KS;
    const int NC = c1 - c0;

    const int tid = threadIdx.x;
    const int wid = tid >> 5;
    const int lane = tid & 31;
    const int g = lane >> 2;
    const int t = lane & 3;
    const int m0 = wid * 16;

    // loader slots: 8 threads per row (float4 cols), 32 rows per pass
    const int lo = tid >> 3;        // row 0..31
    const int lkq = tid & 7;        // float4 col within 32-wide chunk

    auto issue = [&](int c, float* buf) {
        #pragma unroll
        for (int i = 0; i < 4; i++) {
            int row = lo + i * 32;
            uint32_t dst = sm_u32(&buf[row * ROWPAD + lkq * 4]);
            const float* src = W + (size_t)(obase + row) * KDIM + c * KK + lkq * 4;
            CP_ASYNC16(dst, src);
        }
        {
            uint32_t dx = sm_u32(&buf[X_OFF + lo * ROWPAD + lkq * 4]);
            const float* sx = X + (size_t)lo * KDIM + c * KK + lkq * 4;
            CP_ASYNC16(dx, sx);
        }
        CP_COMMIT();
    };

    int issued = 0;
    #pragma unroll
    for (int i = 0; i < NSTAGE; i++)
        if (issued < NC) { issue(c0 + issued, sm + (issued & 3) * SBUF); issued++; }

    float d[4][4];
    #pragma unroll
    for (int nt = 0; nt < 4; nt++)
        #pragma unroll
        for (int r = 0; r < 4; r++) d[nt][r] = 0.0f;

    for (int idx = 0; idx < NC; idx++) {
        const int pend = issued - idx - 1;
        if (pend >= 3)      asm volatile("cp.async.wait_group 3;");
        else if (pend == 2) asm volatile("cp.async.wait_group 2;");
        else if (pend == 1) asm volatile("cp.async.wait_group 1;");
        else                asm volatile("cp.async.wait_group 0;");
        __syncthreads();

        const float* Ws = sm + (idx & 3) * SBUF;
        const float* Xs = Ws + X_OFF;

        #pragma unroll
        for (int ks = 0; ks < 4; ks++) {
            const int k0 = ks * 8;
            const float* wr = Ws + m0 * ROWPAD + k0;
            uint32_t a0 = __float_as_uint(wr[g * ROWPAD + t]);
            uint32_t a1 = __float_as_uint(wr[(g + 8) * ROWPAD + t]);
            uint32_t a2 = __float_as_uint(wr[g * ROWPAD + t + 4]);
            uint32_t a3 = __float_as_uint(wr[(g + 8) * ROWPAD + t + 4]);
            #pragma unroll
            for (int nt = 0; nt < 4; nt++) {
                const int brow = (nt * 8 + g) * ROWPAD + k0;
                uint32_t b0 = __float_as_uint(Xs[brow + t]);
                uint32_t b1 = __float_as_uint(Xs[brow + t + 4]);
                mma_tf32(d[nt], a0, a1, a2, a3, b0, b1);
            }
        }
        __syncthreads();
        if (issued < NC) { issue(c0 + issued, sm + (issued & 3) * SBUF); issued++; }
    }

    // Epilogue: D fragment (m16 x n8): d0:(g,2t) d1:(g,2t+1) d2:(g+8,2t)
    // d3:(g+8,2t+1); rows = o, cols = batch.
    const int slab = blockIdx.y * KS + s;
    const int o = obase + m0 + g;
    #pragma unroll
    for (int nt = 0; nt < 4; nt++) {
        const int bb = nt * 8 + 2 * t;
        g_part[slab][bb][o]         = d[nt][0] * BIASC2;
        g_part[slab][bb + 1][o]     = d[nt][1] * BIASC2;
        g_part[slab][bb][o + 8]     = d[nt][2] * BIASC2;
        g_part[slab][bb + 1][o + 8] = d[nt][3] * BIASC2;
    }
}

// ---------------------------------------------------------------------------
// Moments kernel (slabs: k=6..11, v=12..17)
// ---------------------------------------------------------------------------
__global__ __launch_bounds__(256) void moments_kernel(
    const float* __restrict__ bk, const float* __restrict__ bv)
{
    extern __shared__ float dsm[];
    float* ksm = dsm;                 // [N]
    float* vsm = dsm + N;             // [N]
    float* rep = dsm + 2 * N;         // [8][NBINS][10]
    __shared__ float red[16];

    const int b = blockIdx.x;
    const int tid = threadIdx.x;
    const int w = tid >> 5;
    const int lane = tid & 31;

    float kmn = 1e30f, kmx = -1e30f;
    for (int j = tid; j < N; j += 256) {
        float kv = bk[j], vv = bv[j];
        #pragma unroll
        for (int s = 0; s < KS_QKV; s++) {
            kv += g_part[KS_QKV + s][b][j];
            vv += g_part[2 * KS_QKV + s][b][j];
        }
        ksm[j] = kv;
        vsm[j] = vv;
        kmn = fminf(kmn, kv);
        kmx = fmaxf(kmx, kv);
    }
    #pragma unroll
    for (int d = 16; d > 0; d >>= 1) {
        kmn = fminf(kmn, __shfl_xor_sync(0xffffffffu, kmn, d));
        kmx = fmaxf(kmx, __shfl_xor_sync(0xffffffffu, kmx, d));
    }
    if (lane == 0) { red[w] = kmn; red[8 + w] = kmx; }

    for (int tt = tid; tt < 8 * NBINS * 10; tt += 256) rep[tt] = 0.0f;
    __syncthreads();

    float bmn = red[0], bmx = red[8];
    #pragma unroll
    for (int ww = 1; ww < 8; ww++) {
        bmn = fminf(bmn, red[ww]);
        bmx = fmaxf(bmx, red[8 + ww]);
    }
    float range = fmaxf(bmx - bmn, 1e-6f);
    float dlt = exp2f(ceilf(log2f(range / 126.0f)));
    float kmin_a = floorf(bmn / dlt) * dlt;
    float inv_d = 1.0f / dlt;

    float* myrep = rep + w * (NBINS * 10);
    for (int j = tid; j < N; j += 256) {
        float k = ksm[j], v = vsm[j];
        float cf = (k - kmin_a) * inv_d;
        int c = (int)cf;
        c = max(0, min(NBINS - 1, c));
        float eps = k - fmaf((float)c + 0.5f, dlt, kmin_a);
        float p1 = eps;
        float p2 = 0.5f * eps * eps;
        float p3 = p2 * eps * (1.0f / 3.0f);
        float p4 = p3 * eps * 0.25f;
        float* r = myrep + c * 10;
        atomicAdd(r + 0, 1.0f);
        atomicAdd(r + 1, p1);
        atomicAdd(r + 2, p2);
        atomicAdd(r + 3, p3);
        atomicAdd(r + 4, p4);
        atomicAdd(r + 5, v);
        atomicAdd(r + 6, v * p1);
        atomicAdd(r + 7, v * p2);
        atomicAdd(r + 8, v * p3);
        atomicAdd(r + 9, v * p4);
    }
    __syncthreads();

    if (tid < NBINS) {
        int c = tid;
        float m[10];
        #pragma unroll
        for (int mm = 0; mm < 10; mm++) {
            float sum = 0.0f;
            #pragma unroll
            for (int ww = 0; ww < 8; ww++)
                sum += rep[ww * (NBINS * 10) + c * 10 + mm];
            m[mm] = sum;
        }
        g_mD[b][c] = make_float4(m[0], m[1], m[2], m[3]);
        g_mA[b][c] = make_float4(m[5], m[6], m[7], m[8]);
        g_mE[b][c] = make_float2(m[4], m[9]);
        if (c == 0)
            g_binfo[b] = make_float2(kmin_a + 0.5f * dlt, dlt);
    }
}

// ---------------------------------------------------------------------------
// Attention via bin moments + first SiLU. Geometric exp recurrence: bins are
// equidistant so e_{c+2} = e_c * r2 with r2 = exp2(qL*2*dlt) — replaces
// per-bin MUFU with one FMUL. 2-bin unroll, independent (e, dn) chains.
// ---------------------------------------------------------------------------
__global__ __launch_bounds__(256) void attn2_kernel(
    const float* __restrict__ X, const float* __restrict__ bq)
{
    __shared__ uint64_t sDA[NBINS * 5];   // [c][m]: pair (D_m, A_m)
    const int b = blockIdx.y;
    const int tid = threadIdx.x;

    if (tid < NBINS) {
        float4 D = g_mD[b][tid];
        float4 A = g_mA[b][tid];
        float2 E = g_mE[b][tid];
        sDA[tid * 5 + 0] = packf2(D.x, A.x);
        sDA[tid * 5 + 1] = packf2(D.y, A.y);
        sDA[tid * 5 + 2] = packf2(D.z, A.z);
        sDA[tid * 5 + 3] = packf2(D.w, A.w);
        sDA[tid * 5 + 4] = packf2(E.x, E.y);
    }
    __syncthreads();

    const int i = blockIdx.x * 256 + tid;
    float q = bq[i];
    #pragma unroll
    for (int s = 0; s < KS_QKV; s++) q += g_part[s][b][i];

    const float2 info = g_binfo[b];
    const float kc0 = info.x;
    const float dlt = info.y;
    const float qL = q * LOG2E;
    const uint64_t qq = packf2(q, q);

    float e0 = fast_exp2(qL * kc0);
    float e1 = fast_exp2(qL * (kc0 + dlt));
    const float r2 = fast_exp2(qL * (2.0f * dlt));

    uint64_t dn0 = 0ull, dn1 = 0ull;
    #pragma unroll 4
    for (int c = 0; c < NBINS / 2; c++) {
        const uint64_t* m0 = &sDA[(2 * c) * 5];
        const uint64_t* m1 = &sDA[(2 * c + 1) * 5];
        uint64_t p0 = fma2(m0[4], qq, m0[3]);
        uint64_t p1 = fma2(m1[4], qq, m1[3]);
        p0 = fma2(p0, qq, m0[2]);
        p1 = fma2(p1, qq, m1[2]);
        p0 = fma2(p0, qq, m0[1]);
        p1 = fma2(p1, qq, m1[1]);
        p0 = fma2(p0, qq, m0[0]);
        p1 = fma2(p1, qq, m1[0]);
        dn0 = fma2(packf2(e0, e0), p0, dn0);
        dn1 = fma2(packf2(e1, e1), p1, dn1);
        e0 *= r2;
        e1 *= r2;
    }
    float den0, num0, den1, num1;
    unpackf2(dn0, den0, num0);
    unpackf2(dn1, den1, num1);
    float den = den0 + den1;
    float num = num0 + num1;

    float att = num / den;
    float z = X[(size_t)b * N + i] + att;
    float sg = 1.0f / (1.0f + fast_exp2(-z * LOG2E));
    g_h[b][i] = z * sg;
}

// ---------------------------------------------------------------------------
// Final reduce: out = silu(h + (h @ Wp^T + bp))
// ---------------------------------------------------------------------------
__global__ __launch_bounds__(256) void final_kernel(
    const float* __restrict__ bp, float* __restrict__ out)
{
    const int idx = blockIdx.x * 256 + threadIdx.x;
    const int b = idx >> 12;
    const int o = idx & (N - 1);
    float p = bp[o];
    #pragma unroll
    for (int s = 0; s < SLABS; s++) p += g_part[s][b][o];
    float z = g_h[b][o] + p;
    float sg = 1.0f / (1.0f + fast_exp2(-z * LOG2E));
    out[idx] = z * sg;
}

// ---------------------------------------------------------------------------
extern "C" void kernel_launch(void* const* d_in, const int* in_sizes, int n_in,
                              void* d_out, int out_size)
{
    const float* x  = (const float*)d_in[0];
    const float* Wq = (const float*)d_in[1];
    const float* bq = (const float*)d_in[2];
    const float* Wk = (const float*)d_in[3];
    const float* bk = (const float*)d_in[4];
    const float* Wv = (const float*)d_in[5];
    const float* bv = (const float*)d_in[6];
    const float* Wp = (const float*)d_in[7];
    const float* bp = (const float*)d_in[8];
    float* out = (float*)d_out;

    cudaFuncSetAttribute(gemm_kernel,
                         cudaFuncAttributeMaxDynamicSharedMemorySize, GEMM_SMEM);
    const int mom_smem = (2 * N + 8 * NBINS * 10) * (int)sizeof(float);
    cudaFuncSetAttribute(moments_kernel,
                         cudaFuncAttributeMaxDynamicSharedMemorySize, mom_smem);

    void* hptr = nullptr;
    cudaGetSymbolAddress(&hptr, g_h);

    // q,k,v GEMMs: slabs q=0..5, k=6..11, v=12..17
    gemm_kernel<<<dim3(N / TO, 3, KS_QKV), 256, GEMM_SMEM>>>(
        x, Wq, Wk, Wv, KS_QKV);
    // per-batch bin moments
    moments_kernel<<<B, 256, mom_smem>>>(bk, bv);
    // attention + silu -> g_h (q: slabs 0..5)
    attn2_kernel<<<dim3(N / 256, B), 256>>>(x, bq);
    // projection GEMM on h: slabs 0..17
    gemm_kernel<<<dim3(N / TO, 1, KS_P), 256, GEMM_SMEM>>>(
        (const float*)hptr, Wp, Wp, Wp, KS_P);
    // final reduce + silu
    final_kernel<<<(B * N) / 256, 256>>>(bp, out);
}